// round 2
// baseline (speedup 1.0000x reference)
#include <cuda_runtime.h>

// Problem constants
#define DIM    256
#define NEMB   8192
#define NROWS  16384            // 16*32*32
#define DECAYF 0.99f
#define OMDEC  0.01f
#define EPSF   1e-5f

// Output layout (flattened concatenation of reference return tuple, all fp32)
#define OFF_Q    0ul                      // quantize_st: 4194304
#define OFF_DIFF 4194304ul                // diff: 1
#define OFF_IND  4194305ul                // embed_ind: 16384 (as float)
#define OFF_NE   4210689ul                // new_embedding: 2097152
#define OFF_NCS  6307841ul                // new_cluster_size: 8192
#define OFF_NEA  6316033ul                // new_embedding_avg: 2097152

// Device scratch (no dynamic allocation allowed)
__device__ float g_Et[(size_t)NEMB * DIM];        // embedding transposed [n_embed, dim]
__device__ float g_halfnorm[NEMB];                // 0.5 * ||e_j||^2
__device__ int   g_ind[NROWS];
__device__ float g_embed_sum[(size_t)DIM * NEMB]; // segment sum of z rows, [dim, n_embed]
__device__ float g_onehot[NEMB];
__device__ float g_scal[2];                       // [0]=diff_sum, [1]=n_sum

// ---------------------------------------------------------------------------
// Zero the accumulators (must re-run on every graph replay)
// ---------------------------------------------------------------------------
__global__ void zero_kernel() {
    int i = blockIdx.x * blockDim.x + threadIdx.x;
    int stride = gridDim.x * blockDim.x;
    for (size_t k = i; k < (size_t)DIM * NEMB; k += stride) g_embed_sum[k] = 0.0f;
    if (i < NEMB) g_onehot[i] = 0.0f;
    if (i < 2)    g_scal[i]   = 0.0f;
}

// ---------------------------------------------------------------------------
// Transpose embedding [DIM, NEMB] -> Et [NEMB, DIM]
// ---------------------------------------------------------------------------
__global__ void transpose_kernel(const float* __restrict__ E) {
    __shared__ float tile[32][33];
    int jx = blockIdx.x * 32;   // code base
    int dy = blockIdx.y * 32;   // dim base
    int tx = threadIdx.x;       // 0..31
    #pragma unroll
    for (int r = threadIdx.y; r < 32; r += 8)
        tile[r][tx] = E[(size_t)(dy + r) * NEMB + jx + tx];
    __syncthreads();
    #pragma unroll
    for (int r = threadIdx.y; r < 32; r += 8)
        g_Et[(size_t)(jx + r) * DIM + dy + tx] = tile[tx][r];
}

// ---------------------------------------------------------------------------
// Per-code half squared norm from Et (contiguous rows)
// ---------------------------------------------------------------------------
__global__ void norm_kernel() {
    int w    = threadIdx.x >> 5;
    int lane = threadIdx.x & 31;
    int j = blockIdx.x * 8 + w;
    const float4* e4 = (const float4*)(g_Et + (size_t)j * DIM);
    float s = 0.0f;
    float4 v = e4[lane];
    s += v.x * v.x + v.y * v.y + v.z * v.z + v.w * v.w;
    v = e4[lane + 32];
    s += v.x * v.x + v.y * v.y + v.z * v.z + v.w * v.w;
    #pragma unroll
    for (int off = 16; off; off >>= 1) s += __shfl_down_sync(0xffffffffu, s, off);
    if (lane == 0) g_halfnorm[j] = 0.5f * s;
}

// ---------------------------------------------------------------------------
// Fused distance GEMM + argmax.
// Block: 256 threads, tile 128 rows x 128 codes, 8x8 per thread, BK=8.
// score_j = x.e_j - 0.5*||e_j||^2 ; argmin dist == argmax score.
// ---------------------------------------------------------------------------
__global__ __launch_bounds__(256, 2) void argmax_kernel(const float* __restrict__ z) {
    __shared__ __align__(16) float As[8 * 132];
    __shared__ __align__(16) float Bs[8 * 132];
    __shared__ float redS[128 * 16];
    __shared__ int   redI[128 * 16];

    const int t  = threadIdx.x;
    const int tx = t & 15;       // code group
    const int ty = t >> 4;       // row group
    const int m0 = blockIdx.x * 128;

    const float4* z4  = (const float4*)(z + (size_t)m0 * DIM);
    const int arow = t >> 1;     // 0..127
    const int aseg = t & 1;      // 0..1   (2 float4 per 8-wide k slice)
    const int bcol = t >> 1;
    const int bseg = t & 1;

    float best[8];
    int   bidx[8];
    #pragma unroll
    for (int i = 0; i < 8; i++) { best[i] = -3.0e38f; bidx[i] = 0; }

    for (int nt = 0; nt < NEMB / 128; nt++) {
        const int n0 = nt * 128;
        float acc[8][8];
        #pragma unroll
        for (int i = 0; i < 8; i++)
            #pragma unroll
            for (int j = 0; j < 8; j++) acc[i][j] = 0.0f;

        for (int kt = 0; kt < DIM / 8; kt++) {
            // Load A tile: rows [m0,m0+128), k slice [kt*8, kt*8+8) -> As[k][row]
            {
                float4 v = z4[(size_t)arow * 64 + (size_t)kt * 2 + aseg];
                int kb = aseg * 4;
                As[(kb + 0) * 132 + arow] = v.x;
                As[(kb + 1) * 132 + arow] = v.y;
                As[(kb + 2) * 132 + arow] = v.z;
                As[(kb + 3) * 132 + arow] = v.w;
            }
            // Load B tile: codes [n0,n0+128), same k slice -> Bs[k][col]
            {
                const float4* et4 = (const float4*)(g_Et + (size_t)(n0 + bcol) * DIM + kt * 8);
                float4 v = et4[bseg];
                int kb = bseg * 4;
                Bs[(kb + 0) * 132 + bcol] = v.x;
                Bs[(kb + 1) * 132 + bcol] = v.y;
                Bs[(kb + 2) * 132 + bcol] = v.z;
                Bs[(kb + 3) * 132 + bcol] = v.w;
            }
            __syncthreads();

            #pragma unroll
            for (int k = 0; k < 8; k++) {
                float a[8], b[8];
                float4 t0 = *(const float4*)&As[k * 132 + ty * 8];
                float4 t1 = *(const float4*)&As[k * 132 + ty * 8 + 4];
                a[0] = t0.x; a[1] = t0.y; a[2] = t0.z; a[3] = t0.w;
                a[4] = t1.x; a[5] = t1.y; a[6] = t1.z; a[7] = t1.w;
                float4 u0 = *(const float4*)&Bs[k * 132 + tx * 8];
                float4 u1 = *(const float4*)&Bs[k * 132 + tx * 8 + 4];
                b[0] = u0.x; b[1] = u0.y; b[2] = u0.z; b[3] = u0.w;
                b[4] = u1.x; b[5] = u1.y; b[6] = u1.z; b[7] = u1.w;
                #pragma unroll
                for (int i = 0; i < 8; i++)
                    #pragma unroll
                    for (int j = 0; j < 8; j++)
                        acc[i][j] = fmaf(a[i], b[j], acc[i][j]);
            }
            __syncthreads();
        }

        // Epilogue: subtract 0.5||e||^2 and fold into running argmax
        #pragma unroll
        for (int j = 0; j < 8; j++) {
            int code = n0 + tx * 8 + j;
            float hn = __ldg(&g_halfnorm[code]);
            #pragma unroll
            for (int i = 0; i < 8; i++) {
                float s = acc[i][j] - hn;
                if (s > best[i]) { best[i] = s; bidx[i] = code; }
            }
        }
    }

    // Cross-thread reduction per row (16 code-groups per row)
    #pragma unroll
    for (int i = 0; i < 8; i++) {
        redS[(ty * 8 + i) * 16 + tx] = best[i];
        redI[(ty * 8 + i) * 16 + tx] = bidx[i];
    }
    __syncthreads();
    if (t < 128) {
        float b = redS[t * 16];
        int  bi = redI[t * 16];
        #pragma unroll
        for (int x = 1; x < 16; x++) {
            float s  = redS[t * 16 + x];
            int   si = redI[t * 16 + x];
            if (s > b || (s == b && si < bi)) { b = s; bi = si; }
        }
        g_ind[m0 + t] = bi;   // first-min tie-break preserved (matches jnp.argmin)
    }
}

// ---------------------------------------------------------------------------
// Gather quantize rows, write quantize_st + embed_ind, accumulate diff and
// segment sums (onehot count, per-dim z sums via spread atomics).
// One warp per row.
// ---------------------------------------------------------------------------
__global__ void gather_kernel(const float* __restrict__ z, float* __restrict__ out) {
    int w    = threadIdx.x >> 5;
    int lane = threadIdx.x & 31;
    int row  = blockIdx.x * 8 + w;
    int ind  = g_ind[row];

    const float4* zr = (const float4*)(z + (size_t)row * DIM);
    const float4* qr = (const float4*)(g_Et + (size_t)ind * DIM);
    float4* orow = (float4*)(out + OFF_Q + (size_t)row * DIM);

    float local = 0.0f;
    #pragma unroll
    for (int s = 0; s < 2; s++) {
        int c = lane + s * 32;            // float4 index 0..63
        float4 zv = zr[c];
        float4 qv = qr[c];
        float dx = qv.x - zv.x, dy = qv.y - zv.y, dz = qv.z - zv.z, dw = qv.w - zv.w;
        float4 ov;                         // z + (q - z), rounded like the reference
        ov.x = zv.x + dx; ov.y = zv.y + dy; ov.z = zv.z + dz; ov.w = zv.w + dw;
        orow[c] = ov;
        local += dx * dx + dy * dy + dz * dz + dw * dw;
        int d = c * 4;
        atomicAdd(&g_embed_sum[(size_t)(d + 0) * NEMB + ind], zv.x);
        atomicAdd(&g_embed_sum[(size_t)(d + 1) * NEMB + ind], zv.y);
        atomicAdd(&g_embed_sum[(size_t)(d + 2) * NEMB + ind], zv.z);
        atomicAdd(&g_embed_sum[(size_t)(d + 3) * NEMB + ind], zv.w);
    }
    #pragma unroll
    for (int off = 16; off; off >>= 1) local += __shfl_down_sync(0xffffffffu, local, off);
    if (lane == 0) {
        atomicAdd(&g_scal[0], local);
        atomicAdd(&g_onehot[ind], 1.0f);
        out[OFF_IND + row] = (float)ind;
    }
}

// ---------------------------------------------------------------------------
// new_cluster_size + its global sum n
// ---------------------------------------------------------------------------
__global__ void cluster_kernel(const float* __restrict__ cs, float* __restrict__ out) {
    int j = blockIdx.x * blockDim.x + threadIdx.x;
    float ncs = cs[j] * DECAYF + OMDEC * g_onehot[j];
    out[OFF_NCS + j] = ncs;
    float s = ncs;
    #pragma unroll
    for (int off = 16; off; off >>= 1) s += __shfl_down_sync(0xffffffffu, s, off);
    __shared__ float red[8];
    int lane = threadIdx.x & 31, w = threadIdx.x >> 5;
    if (lane == 0) red[w] = s;
    __syncthreads();
    if (threadIdx.x == 0) {
        float t = 0.0f;
        #pragma unroll
        for (int i = 0; i < 8; i++) t += red[i];
        atomicAdd(&g_scal[1], t);
    }
}

// ---------------------------------------------------------------------------
// new_embedding_avg, new_embedding, diff scalar
// ---------------------------------------------------------------------------
__global__ void final_kernel(const float* __restrict__ eavg, float* __restrict__ out) {
    size_t idx = (size_t)blockIdx.x * blockDim.x + threadIdx.x;
    int j = (int)(idx & (NEMB - 1));
    float ea = eavg[idx] * DECAYF + OMDEC * g_embed_sum[idx];
    out[OFF_NEA + idx] = ea;
    float n = g_scal[1];
    float ncs = out[OFF_NCS + j];
    float smoothed = (ncs + EPSF) / (n + (float)NEMB * EPSF) * n;
    out[OFF_NE + idx] = ea / smoothed;
    if (idx == 0) out[OFF_DIFF] = g_scal[0] * (1.0f / (float)(NROWS * DIM));
}

// ---------------------------------------------------------------------------
extern "C" void kernel_launch(void* const* d_in, const int* in_sizes, int n_in,
                              void* d_out, int out_size) {
    const float* z    = (const float*)d_in[0];   // [16,32,32,256]
    const float* emb  = (const float*)d_in[1];   // [256, 8192]
    const float* cs   = (const float*)d_in[2];   // [8192]
    const float* eavg = (const float*)d_in[3];   // [256, 8192]
    float* out = (float*)d_out;

    zero_kernel<<<2048, 256>>>();
    transpose_kernel<<<dim3(NEMB / 32, DIM / 32), dim3(32, 8)>>>(emb);
    norm_kernel<<<NEMB / 8, 256>>>();
    argmax_kernel<<<NROWS / 128, 256>>>(z);
    gather_kernel<<<NROWS / 8, 256>>>(z, out);
    cluster_kernel<<<NEMB / 256, 256>>>(cs, out);
    final_kernel<<<(DIM * NEMB) / 256, 256>>>(eavg, out);
}

// round 9
// speedup vs baseline: 4.6539x; 4.6539x over previous
#include <cuda_runtime.h>
#include <cuda_bf16.h>
#include <cstdint>

// Problem constants
#define DIM    256
#define NEMB   8192
#define NROWS  16384            // 16*32*32
#define DECAYF 0.99f
#define OMDEC  0.01f
#define EPSF   1e-5f
#define MARGIN 1.0f
#define CCAP   32               // candidates per (row, slot)
#define NSLOT  8                // slots per row (2 nwarp x 4 lane%4)

// Output layout (flattened concatenation of reference return tuple, all fp32)
#define OFF_Q    0ul
#define OFF_DIFF 4194304ul
#define OFF_IND  4194305ul
#define OFF_NE   4210689ul
#define OFF_NCS  6307841ul
#define OFF_NEA  6316033ul

// ---------------------------------------------------------------------------
// Device scratch
// ---------------------------------------------------------------------------
__device__ float          g_Et[(size_t)NEMB * DIM];     // embedding transposed fp32
__device__ __nv_bfloat16  g_Bh[(size_t)NEMB * DIM];     // embedding transposed bf16
__device__ __nv_bfloat16  g_Ah[(size_t)NROWS * DIM];    // z rows bf16
__device__ float          g_halfnorm[NEMB];             // 0.5*||e||^2 fp32
__device__ int            g_cand[(size_t)NROWS * NSLOT * CCAP];
__device__ int            g_ccnt[(size_t)NROWS * NSLOT];
__device__ int            g_ind[NROWS];
__device__ float          g_embed_sum[(size_t)DIM * NEMB];
__device__ float          g_onehot[NEMB];
__device__ float          g_scal[2];                    // [0]=diff_sum, [1]=n_sum

// ---------------------------------------------------------------------------
// PTX helpers — ONLY base-target instructions (cp.async / ldmatrix / mma.sync)
// ---------------------------------------------------------------------------
__device__ __forceinline__ uint32_t smem_u32(const void* p) {
    uint32_t a;
    asm("{ .reg .u64 t; cvta.to.shared.u64 t, %1; cvt.u32.u64 %0, t; }" : "=r"(a) : "l"(p));
    return a;
}
#define SW128(x) ((x) ^ (((x) >> 3) & 0x70))
#define CP_ASYNC16(dst, src) \
    asm volatile("cp.async.cg.shared.global [%0], [%1], 16;" :: "r"(dst), "l"(src) : "memory")
#define CP_COMMIT() asm volatile("cp.async.commit_group;" ::: "memory")
#define CP_WAIT0()  asm volatile("cp.async.wait_group 0;" ::: "memory")

#define LDSM4(r, addr) \
    asm volatile("ldmatrix.sync.aligned.m8n8.x4.shared.b16 {%0,%1,%2,%3}, [%4];" \
        : "=r"((r)[0]), "=r"((r)[1]), "=r"((r)[2]), "=r"((r)[3]) : "r"(addr))

#define MMA16816(c, a, b0, b1) \
    asm volatile("mma.sync.aligned.m16n8k16.row.col.f32.bf16.bf16.f32 " \
        "{%0,%1,%2,%3}, {%4,%5,%6,%7}, {%8,%9}, {%0,%1,%2,%3};" \
        : "+f"((c)[0]), "+f"((c)[1]), "+f"((c)[2]), "+f"((c)[3]) \
        : "r"((a)[0]), "r"((a)[1]), "r"((a)[2]), "r"((a)[3]), "r"(b0), "r"(b1))

// ---------------------------------------------------------------------------
// Zero the accumulators
// ---------------------------------------------------------------------------
__global__ void zero_kernel() {
    int i = blockIdx.x * blockDim.x + threadIdx.x;
    int stride = gridDim.x * blockDim.x;
    for (size_t k = i; k < (size_t)DIM * NEMB; k += stride) g_embed_sum[k] = 0.0f;
    if (i < NEMB) g_onehot[i] = 0.0f;
    if (i < 2)    g_scal[i]   = 0.0f;
}

// ---------------------------------------------------------------------------
// Transpose embedding [DIM, NEMB] -> Et [NEMB, DIM] fp32 + bf16
// ---------------------------------------------------------------------------
__global__ void transpose_kernel(const float* __restrict__ E) {
    __shared__ float tile[32][33];
    int jx = blockIdx.x * 32;
    int dy = blockIdx.y * 32;
    int tx = threadIdx.x;
    #pragma unroll
    for (int r = threadIdx.y; r < 32; r += 8)
        tile[r][tx] = E[(size_t)(dy + r) * NEMB + jx + tx];
    __syncthreads();
    #pragma unroll
    for (int r = threadIdx.y; r < 32; r += 8) {
        float v = tile[tx][r];
        size_t o = (size_t)(jx + r) * DIM + dy + tx;
        g_Et[o] = v;
        g_Bh[o] = __float2bfloat16(v);
    }
}

// ---------------------------------------------------------------------------
// z -> bf16
// ---------------------------------------------------------------------------
__global__ void convz_kernel(const float* __restrict__ z) {
    size_t i = (size_t)blockIdx.x * blockDim.x + threadIdx.x;   // one float4
    float4 v = ((const float4*)z)[i];
    __nv_bfloat16* o = g_Ah + i * 4;
    o[0] = __float2bfloat16(v.x); o[1] = __float2bfloat16(v.y);
    o[2] = __float2bfloat16(v.z); o[3] = __float2bfloat16(v.w);
}

// ---------------------------------------------------------------------------
// halfnorm
// ---------------------------------------------------------------------------
__global__ void norm_kernel() {
    int w    = threadIdx.x >> 5;
    int lane = threadIdx.x & 31;
    int j = blockIdx.x * 8 + w;
    const float4* e4 = (const float4*)(g_Et + (size_t)j * DIM);
    float s = 0.0f;
    float4 v = e4[lane];
    s += v.x * v.x + v.y * v.y + v.z * v.z + v.w * v.w;
    v = e4[lane + 32];
    s += v.x * v.x + v.y * v.y + v.z * v.z + v.w * v.w;
    #pragma unroll
    for (int off = 16; off; off >>= 1) s += __shfl_down_sync(0xffffffffu, s, off);
    if (lane == 0) g_halfnorm[j] = 0.5f * s;
}

// ---------------------------------------------------------------------------
// HMMA (mma.sync bf16) distance GEMM + margin-candidate argmax.
// 256 threads = 8 warps: warp w -> mwarp = w&3 (rows), nwarp = w>>2 (cols).
// Tile M=128, N=128/tile, K=256 (A resident in smem, B double-buffered).
// SMEM layout per tile: 4 K-chunks of [128 rows x 64 bf16 = 128B], SW128.
// ---------------------------------------------------------------------------
#define SMEM_A      0
#define SMEM_B0     65536
#define SMEM_B1     131072
#define SMEM_TOTAL  196608

__global__ void __launch_bounds__(256, 1)
hmma_argmax_kernel() {
    extern __shared__ __align__(1024) char smem[];
    uint32_t sb = smem_u32(smem);
    const int tid = threadIdx.x, wid = tid >> 5, lane = tid & 31;
    const int mwarp = wid & 3, nwarp = wid >> 2;
    const int m0 = blockIdx.x * 128;

    // ---- prologue: A tile + B tile 0 ----
    {
        const __nv_bfloat16* Arow = g_Ah + (size_t)m0 * DIM;
        for (int u = tid; u < 4096; u += 256) {
            int chunk = u >> 10, rem = u & 1023, row = rem >> 3, seg = rem & 7;
            uint32_t dst = sb + SMEM_A + chunk * 16384 + SW128(row * 128 + seg * 16);
            CP_ASYNC16(dst, Arow + (size_t)row * DIM + chunk * 64 + seg * 8);
        }
        for (int u = tid; u < 4096; u += 256) {
            int chunk = u >> 10, rem = u & 1023, row = rem >> 3, seg = rem & 7;
            uint32_t dst = sb + SMEM_B0 + chunk * 16384 + SW128(row * 128 + seg * 16);
            CP_ASYNC16(dst, g_Bh + (size_t)row * DIM + chunk * 64 + seg * 8);
        }
        CP_COMMIT(); CP_WAIT0();
    }
    __syncthreads();

    // per-thread row ownership (c-frag layout): rows q, q+8 within each m16
    const int q = lane >> 2;
    int rowIdx[4];
    rowIdx[0] = m0 + mwarp * 32 + q;
    rowIdx[1] = rowIdx[0] + 8;
    rowIdx[2] = rowIdx[0] + 16;
    rowIdx[3] = rowIdx[0] + 24;
    const int slot = nwarp * 4 + (lane & 3);
    const int colb = (lane & 3) * 2;

    float best[4] = {-3.0e38f, -3.0e38f, -3.0e38f, -3.0e38f};
    int   cnt[4]  = {0, 0, 0, 0};

    // A ldmatrix lane row offsets (fixed)
    const int alr = lane & 15;          // row within m16
    const int kseg16 = (lane >> 4) * 16;

    for (int t = 0; t < 64; t++) {
        const uint32_t bbase = sb + ((t & 1) ? SMEM_B1 : SMEM_B0);

        // prefetch next B tile into the other buffer
        if (t + 1 < 64) {
            uint32_t nb = sb + (((t + 1) & 1) ? SMEM_B1 : SMEM_B0);
            const __nv_bfloat16* Brow = g_Bh + (size_t)(t + 1) * 128 * DIM;
            for (int u = tid; u < 4096; u += 256) {
                int chunk = u >> 10, rem = u & 1023, row = rem >> 3, seg = rem & 7;
                CP_ASYNC16(nb + chunk * 16384 + SW128(row * 128 + seg * 16),
                           Brow + (size_t)row * DIM + chunk * 64 + seg * 8);
            }
            CP_COMMIT();
        }

        float acc[2][8][4];
        #pragma unroll
        for (int m = 0; m < 2; m++)
            #pragma unroll
            for (int nb = 0; nb < 8; nb++)
                #pragma unroll
                for (int r = 0; r < 4; r++) acc[m][nb][r] = 0.0f;

        #pragma unroll 4
        for (int ks = 0; ks < 16; ks++) {
            const int kchunk = ks >> 2;
            const int koff = (ks & 3) * 32 + kseg16;
            const uint32_t chbase = kchunk * 16384;

            uint32_t aF[2][4];
            LDSM4(aF[0], sb + SMEM_A + chbase + SW128((mwarp * 32 + alr) * 128 + koff));
            LDSM4(aF[1], sb + SMEM_A + chbase + SW128((mwarp * 32 + 16 + alr) * 128 + koff));

            uint32_t bF[4][4];
            #pragma unroll
            for (int p = 0; p < 4; p++)
                LDSM4(bF[p], bbase + chbase + SW128((nwarp * 64 + p * 16 + alr) * 128 + koff));

            #pragma unroll
            for (int m = 0; m < 2; m++)
                #pragma unroll
                for (int p = 0; p < 4; p++) {
                    MMA16816(acc[m][2 * p],     aF[m], bF[p][0], bF[p][2]);
                    MMA16816(acc[m][2 * p + 1], aF[m], bF[p][1], bF[p][3]);
                }
        }

        // ---- epilogue: scores -> margin-candidate argmax (registers only) ----
        const int n0 = t * 128 + nwarp * 64;
        #pragma unroll
        for (int nb = 0; nb < 8; nb++) {
            const int c0 = n0 + nb * 8 + colb;
            const float hn0 = __ldg(&g_halfnorm[c0]);
            const float hn1 = __ldg(&g_halfnorm[c0 + 1]);
            #pragma unroll
            for (int m = 0; m < 2; m++) {
                float s00 = acc[m][nb][0] - hn0;   // row q,   col c0
                float s01 = acc[m][nb][1] - hn1;   // row q,   col c0+1
                float s10 = acc[m][nb][2] - hn0;   // row q+8, col c0
                float s11 = acc[m][nb][3] - hn1;   // row q+8, col c0+1
                const int r0 = m * 2, r1 = m * 2 + 1;
                if (s00 > best[r0] - MARGIN) {
                    if (cnt[r0] < CCAP)
                        g_cand[((size_t)rowIdx[r0] * NSLOT + slot) * CCAP + cnt[r0]] = c0;
                    cnt[r0]++; if (s00 > best[r0]) best[r0] = s00;
                }
                if (s01 > best[r0] - MARGIN) {
                    if (cnt[r0] < CCAP)
                        g_cand[((size_t)rowIdx[r0] * NSLOT + slot) * CCAP + cnt[r0]] = c0 + 1;
                    cnt[r0]++; if (s01 > best[r0]) best[r0] = s01;
                }
                if (s10 > best[r1] - MARGIN) {
                    if (cnt[r1] < CCAP)
                        g_cand[((size_t)rowIdx[r1] * NSLOT + slot) * CCAP + cnt[r1]] = c0;
                    cnt[r1]++; if (s10 > best[r1]) best[r1] = s10;
                }
                if (s11 > best[r1] - MARGIN) {
                    if (cnt[r1] < CCAP)
                        g_cand[((size_t)rowIdx[r1] * NSLOT + slot) * CCAP + cnt[r1]] = c0 + 1;
                    cnt[r1]++; if (s11 > best[r1]) best[r1] = s11;
                }
            }
        }

        if (t + 1 < 64) CP_WAIT0();
        __syncthreads();
    }

    #pragma unroll
    for (int r = 0; r < 4; r++)
        g_ccnt[(size_t)rowIdx[r] * NSLOT + slot] = cnt[r];
}

// ---------------------------------------------------------------------------
// fp32 rescore of candidates -> exact argmin index. One warp per row.
// ---------------------------------------------------------------------------
__global__ void rescore_kernel(const float* __restrict__ z) {
    int w = threadIdx.x >> 5, lane = threadIdx.x & 31;
    int row = blockIdx.x * 8 + w;
    const float4* zr = (const float4*)(z + (size_t)row * DIM);
    float4 z0 = zr[lane], z1 = zr[lane + 32];

    int counts[NSLOT];
    bool fallback = false;
    #pragma unroll
    for (int s = 0; s < NSLOT; s++) {
        counts[s] = g_ccnt[(size_t)row * NSLOT + s];
        if (counts[s] > CCAP) fallback = true;
    }

    float best = -3.0e38f;
    int bidx = NEMB;

    auto score = [&](int code) {
        const float4* er = (const float4*)(g_Et + (size_t)code * DIM);
        float4 e0 = er[lane], e1 = er[lane + 32];
        float s = z0.x * e0.x + z0.y * e0.y + z0.z * e0.z + z0.w * e0.w
                + z1.x * e1.x + z1.y * e1.y + z1.z * e1.z + z1.w * e1.w;
        #pragma unroll
        for (int off = 16; off; off >>= 1) s += __shfl_xor_sync(0xffffffffu, s, off);
        return s - g_halfnorm[code];
    };

    if (!fallback) {
        for (int s = 0; s < NSLOT; s++) {
            for (int c = 0; c < counts[s]; c++) {
                int code = g_cand[((size_t)row * NSLOT + s) * CCAP + c];
                float sc = score(code);
                if (sc > best || (sc == best && code < bidx)) { best = sc; bidx = code; }
            }
        }
    } else {
        for (int code = 0; code < NEMB; code++) {
            float sc = score(code);
            if (sc > best || (sc == best && code < bidx)) { best = sc; bidx = code; }
        }
    }
    if (lane == 0) g_ind[row] = bidx;
}

// ---------------------------------------------------------------------------
// Gather quantize rows + diff + segment sums
// ---------------------------------------------------------------------------
__global__ void gather_kernel(const float* __restrict__ z, float* __restrict__ out) {
    int w    = threadIdx.x >> 5;
    int lane = threadIdx.x & 31;
    int row  = blockIdx.x * 8 + w;
    int ind  = g_ind[row];

    const float4* zr = (const float4*)(z + (size_t)row * DIM);
    const float4* qr = (const float4*)(g_Et + (size_t)ind * DIM);
    float4* orow = (float4*)(out + OFF_Q + (size_t)row * DIM);

    float local = 0.0f;
    #pragma unroll
    for (int s = 0; s < 2; s++) {
        int c = lane + s * 32;
        float4 zv = zr[c];
        float4 qv = qr[c];
        float dx = qv.x - zv.x, dy = qv.y - zv.y, dz = qv.z - zv.z, dw = qv.w - zv.w;
        float4 ov;
        ov.x = zv.x + dx; ov.y = zv.y + dy; ov.z = zv.z + dz; ov.w = zv.w + dw;
        orow[c] = ov;
        local += dx * dx + dy * dy + dz * dz + dw * dw;
        int d = c * 4;
        atomicAdd(&g_embed_sum[(size_t)(d + 0) * NEMB + ind], zv.x);
        atomicAdd(&g_embed_sum[(size_t)(d + 1) * NEMB + ind], zv.y);
        atomicAdd(&g_embed_sum[(size_t)(d + 2) * NEMB + ind], zv.z);
        atomicAdd(&g_embed_sum[(size_t)(d + 3) * NEMB + ind], zv.w);
    }
    #pragma unroll
    for (int off = 16; off; off >>= 1) local += __shfl_down_sync(0xffffffffu, local, off);
    if (lane == 0) {
        atomicAdd(&g_scal[0], local);
        atomicAdd(&g_onehot[ind], 1.0f);
        out[OFF_IND + row] = (float)ind;
    }
}

__global__ void cluster_kernel(const float* __restrict__ cs, float* __restrict__ out) {
    int j = blockIdx.x * blockDim.x + threadIdx.x;
    float ncs = cs[j] * DECAYF + OMDEC * g_onehot[j];
    out[OFF_NCS + j] = ncs;
    float s = ncs;
    #pragma unroll
    for (int off = 16; off; off >>= 1) s += __shfl_down_sync(0xffffffffu, s, off);
    __shared__ float red[8];
    int lane = threadIdx.x & 31, w = threadIdx.x >> 5;
    if (lane == 0) red[w] = s;
    __syncthreads();
    if (threadIdx.x == 0) {
        float t = 0.0f;
        #pragma unroll
        for (int i = 0; i < 8; i++) t += red[i];
        atomicAdd(&g_scal[1], t);
    }
}

__global__ void final_kernel(const float* __restrict__ eavg, float* __restrict__ out) {
    size_t idx = (size_t)blockIdx.x * blockDim.x + threadIdx.x;
    int j = (int)(idx & (NEMB - 1));
    float ea = eavg[idx] * DECAYF + OMDEC * g_embed_sum[idx];
    out[OFF_NEA + idx] = ea;
    float n = g_scal[1];
    float ncs = out[OFF_NCS + j];
    float smoothed = (ncs + EPSF) / (n + (float)NEMB * EPSF) * n;
    out[OFF_NE + idx] = ea / smoothed;
    if (idx == 0) out[OFF_DIFF] = g_scal[0] * (1.0f / (float)(NROWS * DIM));
}

// ---------------------------------------------------------------------------
extern "C" void kernel_launch(void* const* d_in, const int* in_sizes, int n_in,
                              void* d_out, int out_size) {
    const float* z    = (const float*)d_in[0];
    const float* emb  = (const float*)d_in[1];
    const float* cs   = (const float*)d_in[2];
    const float* eavg = (const float*)d_in[3];
    float* out = (float*)d_out;

    cudaFuncSetAttribute(hmma_argmax_kernel,
                         cudaFuncAttributeMaxDynamicSharedMemorySize, SMEM_TOTAL);

    zero_kernel<<<2048, 256>>>();
    transpose_kernel<<<dim3(NEMB / 32, DIM / 32), dim3(32, 8)>>>(emb);
    convz_kernel<<<(NROWS * DIM / 4) / 256, 256>>>(z);
    norm_kernel<<<NEMB / 8, 256>>>();
    hmma_argmax_kernel<<<NROWS / 128, 256, SMEM_TOTAL>>>();
    rescore_kernel<<<NROWS / 8, 256>>>(z);
    gather_kernel<<<NROWS / 8, 256>>>(z, out);
    cluster_kernel<<<NEMB / 256, 256>>>(cs, out);
    final_kernel<<<(DIM * NEMB) / 256, 256>>>(eavg, out);
}